// round 2
// baseline (speedup 1.0000x reference)
#include <cuda_runtime.h>
#include <math.h>

#define NT 1024
#define Tn 2048
#define Nn 256
#define Kn 64
#define MS 66   // padded row stride for shared matrices (avoids bank conflicts)

// shared float count:
//  Ls 256*66 + 8 mats 64*66 + 5*256 vec + 256 int + 5*64 vec + 1024 red + 32 sc
#define SMEM_FLOATS (Nn*MS + 8*Kn*MS + 5*Nn + Nn + 5*Kn + 1024 + 32)
#define SMEM_BYTES (SMEM_FLOATS * 4)

#define LOG2PI_F 1.8378770664093453f

// ---------------- 64x64 GEMM helpers (block-cooperative, caller syncs) ------

// C = X*Y (+addM) (+diag)
static __device__ __forceinline__ void gemm_nn(int tid, float* __restrict__ C,
    const float* __restrict__ X, const float* __restrict__ Y,
    const float* __restrict__ addM, const float* __restrict__ addDiag)
{
    int w = tid >> 5, l = tid & 31;
    int a0 = w * 2, a1 = a0 + 1, b0 = l, b1 = l + 32;
    float c00 = 0.f, c01 = 0.f, c10 = 0.f, c11 = 0.f;
#pragma unroll 8
    for (int k = 0; k < Kn; ++k) {
        float x0 = X[a0 * MS + k], x1 = X[a1 * MS + k];
        float y0 = Y[k * MS + b0], y1 = Y[k * MS + b1];
        c00 += x0 * y0; c01 += x0 * y1; c10 += x1 * y0; c11 += x1 * y1;
    }
    if (addM) {
        c00 += addM[a0 * MS + b0]; c01 += addM[a0 * MS + b1];
        c10 += addM[a1 * MS + b0]; c11 += addM[a1 * MS + b1];
    }
    if (addDiag) {
        if (a0 == b0) c00 += addDiag[a0];
        if (a0 == b1) c01 += addDiag[a0];
        if (a1 == b0) c10 += addDiag[a1];
        if (a1 == b1) c11 += addDiag[a1];
    }
    C[a0 * MS + b0] = c00; C[a0 * MS + b1] = c01;
    C[a1 * MS + b0] = c10; C[a1 * MS + b1] = c11;
}

// C = X*Y^T (+addM) (+diag)
static __device__ __forceinline__ void gemm_nt(int tid, float* __restrict__ C,
    const float* __restrict__ X, const float* __restrict__ Y,
    const float* __restrict__ addM, const float* __restrict__ addDiag)
{
    int w = tid >> 5, l = tid & 31;
    int a0 = w * 2, a1 = a0 + 1, b0 = l, b1 = l + 32;
    float c00 = 0.f, c01 = 0.f, c10 = 0.f, c11 = 0.f;
#pragma unroll 8
    for (int k = 0; k < Kn; ++k) {
        float x0 = X[a0 * MS + k], x1 = X[a1 * MS + k];
        float y0 = Y[b0 * MS + k], y1 = Y[b1 * MS + k];
        c00 += x0 * y0; c01 += x0 * y1; c10 += x1 * y0; c11 += x1 * y1;
    }
    if (addM) {
        c00 += addM[a0 * MS + b0]; c01 += addM[a0 * MS + b1];
        c10 += addM[a1 * MS + b0]; c11 += addM[a1 * MS + b1];
    }
    if (addDiag) {
        if (a0 == b0) c00 += addDiag[a0];
        if (a0 == b1) c01 += addDiag[a0];
        if (a1 == b0) c10 += addDiag[a1];
        if (a1 == b1) c11 += addDiag[a1];
    }
    C[a0 * MS + b0] = c00; C[a0 * MS + b1] = c01;
    C[a1 * MS + b0] = c10; C[a1 * MS + b1] = c11;
}

// C = X^T * X  (X lower-triangular w/ zero upper part is fine: full k-sum)
static __device__ __forceinline__ void syrk_t(int tid, float* __restrict__ C,
                                              const float* __restrict__ X)
{
    int w = tid >> 5, l = tid & 31;
    int a0 = w * 2, a1 = a0 + 1, b0 = l, b1 = l + 32;
    float c00 = 0.f, c01 = 0.f, c10 = 0.f, c11 = 0.f;
#pragma unroll 8
    for (int k = 0; k < Kn; ++k) {
        float xa0 = X[k * MS + a0], xa1 = X[k * MS + a1];
        float xb0 = X[k * MS + b0], xb1 = X[k * MS + b1];
        c00 += xa0 * xb0; c01 += xa0 * xb1; c10 += xa1 * xb0; c11 += xa1 * xb1;
    }
    C[a0 * MS + b0] = c00; C[a0 * MS + b1] = c01;
    C[a1 * MS + b0] = c10; C[a1 * MS + b1] = c11;
}

// In-place lower Cholesky of 64x64 SPD matrix in shared; writes 2*sum(log diag)
// to *logdetOut. Uses red[0..63] scratch.
static __device__ void chol64(int tid, float* __restrict__ A,
                              float* __restrict__ red, float* __restrict__ logdetOut)
{
    for (int j = 0; j < Kn; ++j) {
        if (tid == 0) A[j * MS + j] = sqrtf(A[j * MS + j]);
        __syncthreads();
        float dj = A[j * MS + j];
        int i = j + 1 + tid;
        if (i < Kn) A[i * MS + j] = A[i * MS + j] / dj;
        __syncthreads();
        int rem = Kn - 1 - j;
        int tot = rem * rem;
        for (int e = tid; e < tot; e += NT) {
            int r = e / rem, c = e - r * rem;
            if (c <= r) {
                int ri = j + 1 + r, ci = j + 1 + c;
                A[ri * MS + ci] -= A[ri * MS + j] * A[ci * MS + j];
            }
        }
        __syncthreads();
    }
    if (tid < Kn) red[tid] = logf(A[tid * MS + tid]);
    __syncthreads();
    if (tid == 0) {
        float s = 0.f;
        for (int i = 0; i < Kn; ++i) s += red[i];
        *logdetOut = 2.f * s;
    }
    __syncthreads();
}

// X = L^{-1} for lower-triangular L (unit handling inside). Upper of X zeroed.
static __device__ void triinv64(int tid, const float* __restrict__ L, float* __restrict__ X)
{
    for (int e = tid; e < Kn * Kn; e += NT) {
        int r = e >> 6, c = e & 63;
        X[r * MS + c] = (r == c) ? 1.f : 0.f;
    }
    __syncthreads();
    for (int k = 0; k < Kn; ++k) {
        float inv = 1.f / L[k * MS + k];
        if (tid <= k) X[k * MS + tid] *= inv;
        __syncthreads();
        int rows = Kn - 1 - k, cols = k + 1;
        int tot = rows * cols;
        for (int e = tid; e < tot; e += NT) {
            int r = e / cols, j = e - r * cols;
            int i = k + 1 + r;
            X[i * MS + j] -= L[i * MS + k] * X[k * MS + j];
        }
        __syncthreads();
    }
}

// ---------------------------------------------------------------------------

__global__ __launch_bounds__(NT, 1)
void kf_kernel(const float* __restrict__ obs, const float* __restrict__ Lam,
               const float* __restrict__ Araw, const float* __restrict__ logQ,
               const float* __restrict__ logR, float* __restrict__ out)
{
    extern __shared__ float sm[];
    float* Ls  = sm;                 // [Nn][MS] current Lambda_t tile
    float* Am  = Ls + Nn * MS;       // scaled A
    float* Pm  = Am + Kn * MS;       // state covariance P
    float* B1  = Pm + Kn * MS;
    float* B2  = B1 + Kn * MS;
    float* B3  = B2 + Kn * MS;
    float* B4  = B3 + Kn * MS;
    float* B5  = B4 + Kn * MS;
    float* B6  = B5 + Kn * MS;
    float* vv  = B6 + Kn * MS;       // innovation v [Nn]
    float* wv  = vv + Nn;            // v/d
    float* wmv = wv + Nn;            // m/d
    float* w2v = wmv + Nn;           // m/d^2
    float* dinv = w2v + Nn;          // 1/d
    int*   midx = (int*)(dinv + Nn); // masked channel indices
    float* zv  = (float*)(midx + Nn);
    float* zpv = zv + Kn;
    float* uv  = zpv + Kn;
    float* xv  = uv + Kn;
    float* qd  = xv + Kn;            // diag Q
    float* red = qd + Kn;            // 1024 scratch
    float* sc  = red + 1024;         // scalars
    int*   sint = (int*)(sc + 24);

    const int tid = threadIdx.x;

    // ---------------- prologue: constants ----------------
    // A_raw into B1 (padded)
    for (int e = tid; e < Kn * Kn; e += NT)
        B1[(e >> 6) * MS + (e & 63)] = Araw[e];
    if (tid < Kn) qd[tid] = expf(logQ[tid]);
    if (tid < Nn) {
        float r = expf(logR[tid]);
        dinv[tid] = 1.f / (r + 1e-4f);
    }
    __syncthreads();
    if (tid == 0) {
        float ld = 0.f;
        for (int i = 0; i < Nn; ++i) ld += logf(1.f / dinv[i]);
        sc[0] = ld;                  // logdet(D) per step (constant)
    }
    // power iteration for sigma_max(A_raw); v in red[0..63], Av in red[256..319]
    if (tid < Kn) red[tid] = 1.f;
    __syncthreads();
#pragma unroll 1
    for (int it = 0; it < 64; ++it) {
        if (tid < Kn) {
            float s = 0.f;
            for (int k = 0; k < Kn; ++k) s += B1[tid * MS + k] * red[k];
            red[256 + tid] = s;
        }
        __syncthreads();
        if (tid < Kn) {
            float s = 0.f;
            for (int k = 0; k < Kn; ++k) s += B1[k * MS + tid] * red[256 + k];
            red[512 + tid] = s;
        }
        __syncthreads();
        if (tid == 0) {
            float n = 0.f;
            for (int i = 0; i < Kn; ++i) n += red[512 + i] * red[512 + i];
            sc[1] = rsqrtf(fmaxf(n, 1e-30f));
        }
        __syncthreads();
        if (tid < Kn) red[tid] = red[512 + tid] * sc[1];
        __syncthreads();
    }
    if (tid < Kn) {
        float s = 0.f;
        for (int k = 0; k < Kn; ++k) s += B1[tid * MS + k] * red[k];
        red[256 + tid] = s;
    }
    __syncthreads();
    if (tid == 0) {
        float n = 0.f;
        for (int i = 0; i < Kn; ++i) n += red[256 + i] * red[256 + i];
        float sigma = sqrtf(n);
        sc[2] = 0.98f / (sigma + 1e-6f);   // scale for A
    }
    __syncthreads();
    {
        float scale = sc[2];
        for (int e = tid; e < Kn * Kn; e += NT) {
            int r = e >> 6, c = e & 63;
            Am[r * MS + c] = scale * B1[r * MS + c];
        }
    }
    // init P = I, z = 0
    for (int e = tid; e < Kn * Kn; e += NT) {
        int r = e >> 6, c = e & 63;
        Pm[r * MS + c] = (r == c) ? 1.f : 0.f;
    }
    if (tid < Kn) zv[tid] = 0.f;
    __syncthreads();

    // ---------------- main sequential filter loop ----------------
#pragma unroll 1
    for (int t = 0; t < Tn; ++t) {
        // load Lambda_t tile (coalesced float4)
        {
            const float4* Lg = (const float4*)(Lam + (size_t)t * Nn * Kn);
            for (int e4 = tid; e4 < (Nn * Kn) / 4; e4 += NT) {
                float4 v4 = Lg[e4];
                int i = e4 >> 4;
                int c = (e4 & 15) << 2;
                float* p = &Ls[i * MS + c];
                p[0] = v4.x; p[1] = v4.y; p[2] = v4.z; p[3] = v4.w;
            }
        }
        // P_pred = A P A^T + Q  (B1 = A*P, B2 = B1*A^T + diagQ)
        gemm_nn(tid, B1, Am, Pm, 0, 0);
        __syncthreads();
        gemm_nt(tid, B2, B1, Am, 0, qd);
        // z_pred = A z
        if (tid < Kn) {
            float s = 0.f;
            for (int k = 0; k < Kn; ++k) s += Am[tid * MS + k] * zv[k];
            zpv[tid] = s;
        }
        __syncthreads();

        // innovation + per-channel weights
        if (tid < Nn) {
            float y = obs[(size_t)t * Nn + tid];
            float yp = 0.f;
            for (int a = 0; a < Kn; ++a) yp += Ls[tid * MS + a] * zpv[a];
            bool nanm = !(y == y);
            float vi = nanm ? 0.f : (y - yp);
            float di = dinv[tid];
            float m = nanm ? 0.f : 1.f;
            vv[tid] = vi;
            wv[tid] = vi * di;
            wmv[tid] = m * di;
            w2v[tid] = m * di * di;
        }
        __syncthreads();
        // masked list + sdv (deterministic serial on tid0)
        if (tid == 0) {
            int cnt = 0;
            float sdv = 0.f;
            for (int i = 0; i < Nn; ++i) {
                if (wmv[i] == 0.f) midx[cnt++] = i;
                sdv += vv[i] * wv[i];
            }
            sint[0] = cnt;
            sc[3] = (float)(Nn - cnt);   // active_N
            sc[4] = sdv;
        }
        // u = L^T (v/d): 64 groups x 16 partials
        {
            int a = tid >> 4, s = tid & 15;
            float part = 0.f;
#pragma unroll 4
            for (int ii = 0; ii < 16; ++ii) {
                int i = ii * 16 + s;
                part += Ls[i * MS + a] * wv[i];
            }
            red[tid] = part;
        }
        __syncthreads();
        if (tid < Kn) {
            float s = 0.f;
            for (int p = 0; p < 16; ++p) s += red[tid * 16 + p];
            uv[tid] = s;
        }
        __syncthreads();

        // Wm = L^T diag(m/d) L  -> B3 ; W2 = L^T diag(m/d^2) L -> B4 (fused)
        {
            int w = tid >> 5, l = tid & 31;
            int a0 = w * 2, a1 = a0 + 1, b0 = l, b1 = l + 32;
            float m00 = 0.f, m01 = 0.f, m10 = 0.f, m11 = 0.f;
            float q00 = 0.f, q01 = 0.f, q10 = 0.f, q11 = 0.f;
#pragma unroll 4
            for (int i = 0; i < Nn; ++i) {
                float cm = wmv[i], c2 = w2v[i];
                float la0 = Ls[i * MS + a0], la1 = Ls[i * MS + a1];
                float lb0 = Ls[i * MS + b0], lb1 = Ls[i * MS + b1];
                float p00 = la0 * lb0, p01 = la0 * lb1;
                float p10 = la1 * lb0, p11 = la1 * lb1;
                m00 += cm * p00; m01 += cm * p01; m10 += cm * p10; m11 += cm * p11;
                q00 += c2 * p00; q01 += c2 * p01; q10 += c2 * p10; q11 += c2 * p11;
            }
            B3[a0 * MS + b0] = m00; B3[a0 * MS + b1] = m01;
            B3[a1 * MS + b0] = m10; B3[a1 * MS + b1] = m11;
            B4[a0 * MS + b0] = q00; B4[a0 * MS + b1] = q01;
            B4[a1 * MS + b0] = q10; B4[a1 * MS + b1] = q11;
        }
        __syncthreads();
        // Wfull -> B5 (Wm + masked channels at weight 1/d); Wr -> B4 = Wm - 1e-4*W2
        {
            int nm = sint[0];
            for (int e = tid; e < Kn * Kn; e += NT) {
                int a = e >> 6, b = e & 63;
                float wmval = B3[a * MS + b];
                float s = wmval;
                for (int j = 0; j < nm; ++j) {
                    int ich = midx[j];
                    s += dinv[ich] * Ls[ich * MS + a] * Ls[ich * MS + b];
                }
                B5[a * MS + b] = s;
                B4[a * MS + b] = wmval - 1e-4f * B4[a * MS + b];
            }
        }
        __syncthreads();

        // chol(P_pred): copy B2 -> B1, factor, logdetP -> sc[5]
        for (int e = tid; e < Kn * Kn; e += NT) {
            int a = e >> 6, b = e & 63;
            B1[a * MS + b] = B2[a * MS + b];
        }
        __syncthreads();
        chol64(tid, B1, red, &sc[5]);
        triinv64(tid, B1, B6);           // B6 = G^{-1}
        syrk_t(tid, B1, B6);             // B1 = P^{-1}
        __syncthreads();
        // M = P^{-1} + Wfull  (into B5)
        for (int e = tid; e < Kn * Kn; e += NT) {
            int a = e >> 6, b = e & 63;
            B5[a * MS + b] += B1[a * MS + b];
        }
        __syncthreads();
        chol64(tid, B5, red, &sc[6]);    // C = chol(M), logdetM -> sc[6]
        triinv64(tid, B5, B1);           // B1 = C^{-1}
        syrk_t(tid, B6, B1);             // B6 = M^{-1}
        __syncthreads();

        // x = M^{-1} u ; quad = u.x
        {
            int a = tid >> 4, s = tid & 15;
            float part = 0.f;
#pragma unroll 4
            for (int ii = 0; ii < 4; ++ii) {
                int k = ii * 16 + s;
                part += B6[a * MS + k] * uv[k];
            }
            red[tid] = part;
        }
        __syncthreads();
        if (tid < Kn) {
            float s = 0.f;
            for (int p = 0; p < 16; ++p) s += red[tid * 16 + p];
            xv[tid] = s;
        }
        __syncthreads();
        if (tid == 0) {
            float q = 0.f;
            for (int i = 0; i < Kn; ++i) q += uv[i] * xv[i];
            sc[7] = q;
        }

        // KGL = Minv*Wm -> B5 ; Ttmp = Minv*Wr -> B1 ; KGRKG = Ttmp*Minv -> B4
        gemm_nn(tid, B5, B6, B3, 0, 0);
        __syncthreads();
        gemm_nn(tid, B1, B6, B4, 0, 0);
        __syncthreads();
        gemm_nn(tid, B4, B1, B6, 0, 0);
        __syncthreads();
        // IKL = I - KGL (in place B5)
        for (int e = tid; e < Kn * Kn; e += NT) {
            int a = e >> 6, b = e & 63;
            float val = B5[a * MS + b];
            B5[a * MS + b] = ((a == b) ? 1.f : 0.f) - val;
        }
        __syncthreads();
        // T2 = IKL * Ppred -> B6 ; Pnew = T2*IKL^T + KGRKG -> B3
        gemm_nn(tid, B6, B5, B2, 0, 0);
        __syncthreads();
        gemm_nt(tid, B3, B6, B5, B4, 0);
        __syncthreads();
        // P = 0.5*(Pnew + Pnew^T)
        for (int e = tid; e < Kn * Kn; e += NT) {
            int a = e >> 6, b = e & 63;
            Pm[a * MS + b] = 0.5f * (B3[a * MS + b] + B3[b * MS + a]);
        }

        // outputs
        if (tid < Kn) {
            float z = zpv[tid] + xv[tid];
            zv[tid] = z;
            out[(size_t)t * (Kn + 1) + tid] = z;
        }
        if (tid == 0) {
            float mahal = sc[4] - sc[7];
            float ll = -0.5f * (sc[3] * LOG2PI_F + sc[0] + sc[5] + sc[6] + mahal);
            if (!(ll == ll)) ll = -1e6f;   // nan_to_num(nan=-1e6)
            out[(size_t)t * (Kn + 1) + Kn] = ll;
        }
        __syncthreads();
    }
}

extern "C" void kernel_launch(void* const* d_in, const int* in_sizes, int n_in,
                              void* d_out, int out_size)
{
    const float* obs  = (const float*)d_in[0];
    const float* Lam  = (const float*)d_in[1];
    const float* Araw = (const float*)d_in[2];
    const float* lQ   = (const float*)d_in[3];
    const float* lR   = (const float*)d_in[4];
    float* out = (float*)d_out;

    cudaFuncSetAttribute(kf_kernel, cudaFuncAttributeMaxDynamicSharedMemorySize,
                         SMEM_BYTES);
    kf_kernel<<<1, NT, SMEM_BYTES>>>(obs, Lam, Araw, lQ, lR, out);
}